// round 2
// baseline (speedup 1.0000x reference)
#include <cuda_runtime.h>
#include <math.h>

#define T_DIM 512
#define B_DIM 128
#define I_DIM 512
#define H_DIM 512

#define BH (B_DIM * H_DIM)           // 65536
#define TBH (T_DIM * B_DIM * H_DIM)  // 33554432

#define NB 128   // persistent blocks (<= SM count, all co-resident)
#define NT 256

// Scratch (static device globals — no runtime allocation).
__device__ float g_A[TBH];    // precomputed x_t @ W0x^T + b0, [T*B, H]
__device__ float g_h1[BH];    // h1 for current step
__device__ float g_c[BH];     // cell state
__device__ int           g_count = 0;
__device__ volatile int  g_sense = 0;

// ---------------------------------------------------------------------------
// Grid barrier (sense reversal). Total barriers per launch MUST be even so
// g_sense returns to 0 for the next graph replay (it does: 2 * T_DIM = 1024).
// ---------------------------------------------------------------------------
__device__ __forceinline__ void grid_barrier(int& sense)
{
    __syncthreads();
    if (threadIdx.x == 0) {
        int s = sense ^ 1;
        __threadfence();
        int arrived = atomicAdd(&g_count, 1);
        if (arrived == NB - 1) {
            g_count = 0;
            __threadfence();
            g_sense = s;
        } else {
            while (g_sense != s) { }
        }
        __threadfence();
    }
    __syncthreads();
    sense ^= 1;
}

// ---------------------------------------------------------------------------
// Precompute: g_A[row, j] = x[row, :] . W0[j, 0:512] + b0[j]
// row in [0, T*B), j in [0, 512). 64x64 tiles, 4x4 per thread, BK=16.
// Smem row stride 68 keeps 16B alignment so the compiler emits LDS.128.
// ---------------------------------------------------------------------------
__global__ void __launch_bounds__(256) precompute_kernel(
    const float* __restrict__ x,
    const float* __restrict__ W0,
    const float* __restrict__ b0)
{
    __shared__ float Xs[16][68];
    __shared__ float Ws[16][68];

    const int tid = threadIdx.x;
    const int bm0 = blockIdx.y * 64;   // rows (t*B + b)
    const int bn0 = blockIdx.x * 64;   // h
    const int tx = tid % 16;
    const int ty = tid / 16;

    float acc[4][4];
#pragma unroll
    for (int i = 0; i < 4; i++)
#pragma unroll
        for (int j = 0; j < 4; j++) acc[i][j] = 0.0f;

    for (int k0 = 0; k0 < I_DIM; k0 += 16) {
#pragma unroll
        for (int i = 0; i < 4; i++) {
            int idx = tid + i * 256;
            int r = idx >> 4, c = idx & 15;
            Xs[c][r] = x[(size_t)(bm0 + r) * I_DIM + k0 + c];
            Ws[c][r] = W0[(size_t)(bn0 + r) * (H_DIM + I_DIM) + k0 + c];
        }
        __syncthreads();
#pragma unroll
        for (int k = 0; k < 16; k++) {
            float a[4], b[4];
#pragma unroll
            for (int i = 0; i < 4; i++) a[i] = Xs[k][ty * 4 + i];
#pragma unroll
            for (int j = 0; j < 4; j++) b[j] = Ws[k][tx * 4 + j];
#pragma unroll
            for (int i = 0; i < 4; i++)
#pragma unroll
                for (int j = 0; j < 4; j++) acc[i][j] = fmaf(a[i], b[j], acc[i][j]);
        }
        __syncthreads();
    }

#pragma unroll
    for (int i = 0; i < 4; i++) {
        size_t row = (size_t)(bm0 + ty * 4 + i);
#pragma unroll
        for (int j = 0; j < 4; j++) {
            int n = bn0 + tx * 4 + j;
            g_A[row * H_DIM + n] = acc[i][j] + b0[n];
        }
    }
}

// ---------------------------------------------------------------------------
// Persistent recurrence kernel. 128 blocks x 256 threads, 2 barriers/step.
// Block (bt, ht): bt in [0,8) covers b-rows bt*16..+16, ht in [0,16) covers
// h-cols ht*32..+32. Each thread owns 2 (b,h) outputs: (ty, tx), (ty+8, tx).
// ---------------------------------------------------------------------------
__global__ void __launch_bounds__(NT, 1) dlstm_persistent(
    const float* __restrict__ cell,
    const float* __restrict__ W0,   // [512][1024]
    const float* __restrict__ W1,   // [2560][512]
    const float* __restrict__ b1,   // [2560]
    float* __restrict__ out)        // [T][B][H] then [B][H] final cell
{
    __shared__ float As[16][17];     // [k][m]
    __shared__ float Bs[5][16][33];  // [gate][k][n] (phase A uses Bs[0])

    const int tid = threadIdx.x;
    const int bid = blockIdx.x;
    const int bt = bid >> 4;        // 0..7
    const int ht = bid & 15;        // 0..15
    const int bm0 = bt * 16;
    const int bn0 = ht * 32;
    const int tx = tid & 31;        // h within tile
    const int ty = tid >> 5;        // 0..7, b within tile (and +8)

    const int sr = tid >> 4;        // staging row 0..15
    const int sc = tid & 15;        // staging k  0..15

    int sense = 0;

    for (int t = 0; t < T_DIM; t++) {
        const float* cprev = (t == 0) ? cell : (const float*)g_c;

        // ---------------- Phase A: h1 = relu(g_A[t] + c @ W0c^T) ----------
        float a0 = 0.0f, a1 = 0.0f;
        for (int k0 = 0; k0 < H_DIM; k0 += 16) {
            As[sc][sr] = cprev[(bm0 + sr) * H_DIM + k0 + sc];
#pragma unroll
            for (int i = 0; i < 2; i++) {
                int idx = tid + i * 256;
                int n = idx >> 4, k = idx & 15;
                Bs[0][k][n] = W0[(size_t)(bn0 + n) * (H_DIM + I_DIM) + I_DIM + k0 + k];
            }
            __syncthreads();
#pragma unroll
            for (int k = 0; k < 16; k++) {
                float b = Bs[0][k][tx];
                a0 = fmaf(As[k][ty], b, a0);
                a1 = fmaf(As[k][ty + 8], b, a1);
            }
            __syncthreads();
        }
        {
            const float* pre = g_A + ((size_t)t * B_DIM + bm0) * H_DIM + bn0;
            g_h1[(bm0 + ty) * H_DIM + bn0 + tx]     = fmaxf(a0 + pre[ty * H_DIM + tx], 0.0f);
            g_h1[(bm0 + ty + 8) * H_DIM + bn0 + tx] = fmaxf(a1 + pre[(ty + 8) * H_DIM + tx], 0.0f);
        }
        grid_barrier(sense);

        // ---------------- Phase B: 5-gate GEMM + fused gate epilogue ------
        float acc[2][5];
#pragma unroll
        for (int i = 0; i < 2; i++)
#pragma unroll
            for (int g = 0; g < 5; g++) acc[i][g] = 0.0f;

        for (int k0 = 0; k0 < H_DIM; k0 += 16) {
            As[sc][sr] = g_h1[(bm0 + sr) * H_DIM + k0 + sc];
#pragma unroll
            for (int i = 0; i < 10; i++) {
                int idx = tid + i * 256;        // 0..2559
                int row = idx >> 4;             // 0..159 = g*32 + n
                int k = idx & 15;
                int gg = row >> 5;
                int n = row & 31;
                Bs[gg][k][n] = W1[(size_t)((gg << 9) + bn0 + n) * H_DIM + k0 + k];
            }
            __syncthreads();
#pragma unroll
            for (int k = 0; k < 16; k++) {
                float h0 = As[k][ty];
                float h1v = As[k][ty + 8];
#pragma unroll
                for (int g = 0; g < 5; g++) {
                    float b = Bs[g][k][tx];
                    acc[0][g] = fmaf(h0, b, acc[0][g]);
                    acc[1][g] = fmaf(h1v, b, acc[1][g]);
                }
            }
            __syncthreads();
        }

        // Gates epilogue: each thread owns its 2 (b,h) cells exclusively.
        {
            int h = bn0 + tx;
            float bb0 = b1[h];
            float bb1 = b1[H_DIM + h];
            float bb2 = b1[2 * H_DIM + h];
            float bb3 = b1[3 * H_DIM + h];
            float bb4 = b1[4 * H_DIM + h];
#pragma unroll
            for (int i = 0; i < 2; i++) {
                int b = bm0 + ty + i * 8;
                float cxa = acc[i][0] + bb0;
                float cxb = acc[i][1] + bb1;
                float hx  = fmaxf(acc[i][2] + bb2, 0.0f);
                float fg  = 1.0f / (1.0f + expf(-(acc[i][3] + bb3)));
                float ig  = 1.0f / (1.0f + expf(-(acc[i][4] + bb4)));
                float cold = cprev[b * H_DIM + h];
                float cn = ig * (fmaxf(cxa, 0.0f) - fmaxf(cxb, 0.0f)) + fg * cold;
                g_c[b * H_DIM + h] = cn;
                out[((size_t)t * B_DIM + b) * H_DIM + h] = hx;
                if (t == T_DIM - 1)
                    out[(size_t)TBH + (size_t)b * H_DIM + h] = cn;
            }
        }
        grid_barrier(sense);
    }
}

// ---------------------------------------------------------------------------
// Launch: exactly 2 kernel nodes in the graph.
// ---------------------------------------------------------------------------
extern "C" void kernel_launch(void* const* d_in, const int* in_sizes, int n_in,
                              void* d_out, int out_size)
{
    const float* x    = (const float*)d_in[0];  // [T, B, I]
    const float* cell = (const float*)d_in[1];  // [1, B, H]
    const float* W0   = (const float*)d_in[2];  // [H, H+I]
    const float* b0   = (const float*)d_in[3];  // [H]
    const float* W1   = (const float*)d_in[4];  // [5H, H]
    const float* b1   = (const float*)d_in[5];  // [5H]
    float* out = (float*)d_out;

    {
        dim3 grid(H_DIM / 64, (T_DIM * B_DIM) / 64);
        precompute_kernel<<<grid, 256>>>(x, W0, b0);
    }
    dlstm_persistent<<<NB, NT>>>(cell, W0, W1, b1, out);
}

// round 3
// speedup vs baseline: 1.0424x; 1.0424x over previous
#include <cuda_runtime.h>
#include <math.h>

#define T_DIM 512
#define B_DIM 128
#define I_DIM 512
#define H_DIM 512

#define BH (B_DIM * H_DIM)           // 65536
#define TBH (T_DIM * B_DIM * H_DIM)  // 33554432

#define NB 128   // persistent blocks (all co-resident, 1/SM)
#define NT 256

// Scratch (static device globals — no runtime allocation).
__device__ float g_A[TBH];    // precomputed x_t @ W0x^T + b0, [T*B, H]
__device__ float g_h1[BH];    // h1 for current step
__device__ float g_c[BH];     // cell state
__device__ int           g_count = 0;
__device__ volatile int  g_sense = 0;

// ---------------------------------------------------------------------------
// Grid barrier (sense reversal). 2*T_DIM = 1024 barriers/launch (even), so
// g_sense returns to 0 for the next graph replay.
// ---------------------------------------------------------------------------
__device__ __forceinline__ void grid_barrier(int& sense)
{
    __syncthreads();
    if (threadIdx.x == 0) {
        int s = sense ^ 1;
        __threadfence();
        int arrived = atomicAdd(&g_count, 1);
        if (arrived == NB - 1) {
            g_count = 0;
            __threadfence();
            g_sense = s;
        } else {
            while (g_sense != s) { }
        }
        __threadfence();
    }
    __syncthreads();
    sense ^= 1;
}

// ---------------------------------------------------------------------------
// Precompute: g_A[row, n] = x[row, :] . W0[n, 0:512] + b0[n]
// 128x64 tiles, 8x4 per thread, BK=16, 256 threads.
// ---------------------------------------------------------------------------
__global__ void __launch_bounds__(256) precompute_kernel(
    const float* __restrict__ x,
    const float* __restrict__ W0,
    const float* __restrict__ b0)
{
    __shared__ __align__(16) float Xs[16][128];
    __shared__ __align__(16) float Ws[16][64];

    const int tid = threadIdx.x;
    const int bm0 = blockIdx.y * 128;
    const int bn0 = blockIdx.x * 64;
    const int tx = tid & 15;
    const int ty = tid >> 4;

    float4 b4 = *reinterpret_cast<const float4*>(&b0[bn0 + tx * 4]);

    float acc[8][4];
#pragma unroll
    for (int i = 0; i < 8; i++)
#pragma unroll
        for (int j = 0; j < 4; j++) acc[i][j] = 0.0f;

    for (int k0 = 0; k0 < I_DIM; k0 += 16) {
        // Stage X tile: 128 rows x 16 k = 512 float4s
#pragma unroll
        for (int i = 0; i < 2; i++) {
            int fid = tid + i * 256;
            int r = fid >> 2;
            int k4 = (fid & 3) * 4;
            float4 v = *reinterpret_cast<const float4*>(&x[(size_t)(bm0 + r) * I_DIM + k0 + k4]);
            Xs[k4 + 0][r] = v.x; Xs[k4 + 1][r] = v.y;
            Xs[k4 + 2][r] = v.z; Xs[k4 + 3][r] = v.w;
        }
        // Stage W tile: 64 rows x 16 k = 256 float4s
        {
            int n = tid >> 2;
            int k4 = (tid & 3) * 4;
            float4 v = *reinterpret_cast<const float4*>(&W0[(size_t)(bn0 + n) * (H_DIM + I_DIM) + k0 + k4]);
            Ws[k4 + 0][n] = v.x; Ws[k4 + 1][n] = v.y;
            Ws[k4 + 2][n] = v.z; Ws[k4 + 3][n] = v.w;
        }
        __syncthreads();
#pragma unroll
        for (int k = 0; k < 16; k++) {
            float4 a0 = *reinterpret_cast<const float4*>(&Xs[k][ty * 8]);
            float4 a1 = *reinterpret_cast<const float4*>(&Xs[k][ty * 8 + 4]);
            float4 w = *reinterpret_cast<const float4*>(&Ws[k][tx * 4]);
            float av[8] = {a0.x, a0.y, a0.z, a0.w, a1.x, a1.y, a1.z, a1.w};
            float wv[4] = {w.x, w.y, w.z, w.w};
#pragma unroll
            for (int i = 0; i < 8; i++)
#pragma unroll
                for (int j = 0; j < 4; j++) acc[i][j] = fmaf(av[i], wv[j], acc[i][j]);
        }
        __syncthreads();
    }

#pragma unroll
    for (int i = 0; i < 8; i++) {
        size_t row = (size_t)(bm0 + ty * 8 + i);
        float4 v = make_float4(acc[i][0] + b4.x, acc[i][1] + b4.y,
                               acc[i][2] + b4.z, acc[i][3] + b4.w);
        *reinterpret_cast<float4*>(&g_A[row * H_DIM + bn0 + tx * 4]) = v;
    }
}

// ---------------------------------------------------------------------------
// Persistent recurrence. 128 blocks x 256 threads. Block (bt,nt): b-rows
// [bt*16,+16), h-cols [nt*32,+32). 256 threads = 4 k-slices (128 k each)
// x 64 threads; per slice thread grid = 4 ty (4 b each) x 16 tx (2 h each).
//
// Shared buffer (10240 floats = 40KB), aliased regions (sync-guarded):
//   phase A k-loop: As_a[4][8][16] @0, Ws_a[4][8][32] @512
//   phase B k-loop: As_b[4][8][16] @0, Bs[4][5][8][32]  @512
//   reductions:     partA[8][4][64] @0 / partB[40][4][64] @0
// ---------------------------------------------------------------------------
#define AS(ksi,kki,r)      ((ksi)*128 + (kki)*16 + (r))
#define WSA(ksi,kki,n)     (512 + (ksi)*256 + (kki)*32 + (n))
#define BSB(ksi,gi,kki,n)  (512 + (ksi)*1280 + (gi)*256 + (kki)*32 + (n))
#define PART(s,ksi,w)      ((s)*256 + (ksi)*64 + (w))

__global__ void __launch_bounds__(NT, 1) dlstm_persistent(
    const float* __restrict__ cell,
    const float* __restrict__ W0,   // [512][1024]
    const float* __restrict__ W1,   // [2560][512]
    const float* __restrict__ b1,   // [2560]
    float* __restrict__ out)        // [T][B][H] then [B][H] final cell
{
    __shared__ __align__(16) float sm[10240];

    const int tid = threadIdx.x;
    const int bid = blockIdx.x;
    const int bm0 = (bid >> 4) * 16;   // b-range
    const int bn0 = (bid & 15) * 32;   // h-range
    const int ks = tid >> 6;           // k-slice 0..3
    const int wt = tid & 63;
    const int ty = wt >> 4;            // 0..3
    const int tx = wt & 15;            // 0..15

    // Staging decompositions (conflict-free STS patterns)
    const int st_r = tid & 15;              // c/h1 tile: row
    const int st_n = tid & 31;              // W tiles: n-col
    const int st_z = tid >> 5;              // 0..7

    int sense = 0;

    for (int t = 0; t < T_DIM; t++) {
        const float* cprev = (t == 0) ? cell : (const float*)g_c;

        // ================= Phase A: h1 = relu(g_A[t] + c @ W0c^T) ==========
        float acca[4][2];
#pragma unroll
        for (int i = 0; i < 4; i++) { acca[i][0] = 0.f; acca[i][1] = 0.f; }

        for (int it = 0; it < 16; it++) {
            // stage cprev tile: [4 slices][8 kk][16 r] = 512 floats
#pragma unroll
            for (int i = 0; i < 2; i++) {
                int e = tid + i * 256;
                int zz = e >> 4;            // 0..31
                int kse = zz >> 3, kk = zz & 7;
                sm[AS(kse, kk, st_r)] =
                    cprev[(bm0 + st_r) * H_DIM + kse * 128 + it * 8 + kk];
            }
            // stage W0c tile: [4][8][32] = 1024 floats
#pragma unroll
            for (int i = 0; i < 4; i++) {
                int idx = i * 8 + st_z;     // 0..31
                int kse = idx >> 3, kk = idx & 7;
                sm[WSA(kse, kk, st_n)] =
                    W0[(size_t)(bn0 + st_n) * (H_DIM + I_DIM) + I_DIM + kse * 128 + it * 8 + kk];
            }
            __syncthreads();
#pragma unroll
            for (int kk = 0; kk < 8; kk++) {
                float4 a = *reinterpret_cast<const float4*>(&sm[AS(ks, kk, ty * 4)]);
                float2 w = *reinterpret_cast<const float2*>(&sm[WSA(ks, kk, tx * 2)]);
                float av[4] = {a.x, a.y, a.z, a.w};
#pragma unroll
                for (int i = 0; i < 4; i++) {
                    acca[i][0] = fmaf(av[i], w.x, acca[i][0]);
                    acca[i][1] = fmaf(av[i], w.y, acca[i][1]);
                }
            }
            __syncthreads();
        }
        // partials -> smem
#pragma unroll
        for (int i = 0; i < 4; i++)
#pragma unroll
            for (int j = 0; j < 2; j++)
                sm[PART(i * 2 + j, ks, wt)] = acca[i][j];
        __syncthreads();
        // reduce 4 slices, add precomputed A, relu, write h1
#pragma unroll
        for (int q = 0; q < 2; q++) {
            int c = tid + q * 256;          // 0..511
            int bl = c >> 5, hl = c & 31;
            int wti = (bl >> 2) * 16 + (hl >> 1);
            int s = (bl & 3) * 2 + (hl & 1);
            float v = sm[PART(s, 0, wti)] + sm[PART(s, 1, wti)]
                    + sm[PART(s, 2, wti)] + sm[PART(s, 3, wti)];
            v += g_A[((size_t)t * B_DIM + bm0 + bl) * H_DIM + bn0 + hl];
            g_h1[(bm0 + bl) * H_DIM + bn0 + hl] = fmaxf(v, 0.0f);
        }
        grid_barrier(sense);

        // ================= Phase B: 5-gate GEMM + fused epilogue ===========
        float acc[4][10];
#pragma unroll
        for (int i = 0; i < 4; i++)
#pragma unroll
            for (int cc = 0; cc < 10; cc++) acc[i][cc] = 0.0f;

        for (int it = 0; it < 16; it++) {
            // stage h1 tile (same pattern as cprev)
#pragma unroll
            for (int i = 0; i < 2; i++) {
                int e = tid + i * 256;
                int zz = e >> 4;
                int kse = zz >> 3, kk = zz & 7;
                sm[AS(kse, kk, st_r)] =
                    g_h1[(bm0 + st_r) * H_DIM + kse * 128 + it * 8 + kk];
            }
            // stage W1 tile: [4 slices][5 gates][8 kk][32 hh] = 5120 floats.
            // Each thread: slice ks, rows hh = wt&31, k-half khalf = wt>>5.
            {
                int hh = wt & 31;
                int khalf = wt >> 5;             // 0 or 1
                int kk4 = khalf * 4;             // k offset 0 or 4
#pragma unroll
                for (int g = 0; g < 5; g++) {
                    float4 v = *reinterpret_cast<const float4*>(
                        &W1[(size_t)((g << 9) + bn0 + hh) * H_DIM + ks * 128 + it * 8 + kk4]);
                    sm[BSB(ks, g, kk4 + 0, hh)] = v.x;
                    sm[BSB(ks, g, kk4 + 1, hh)] = v.y;
                    sm[BSB(ks, g, kk4 + 2, hh)] = v.z;
                    sm[BSB(ks, g, kk4 + 3, hh)] = v.w;
                }
            }
            __syncthreads();
#pragma unroll
            for (int kk = 0; kk < 8; kk++) {
                float4 a = *reinterpret_cast<const float4*>(&sm[AS(ks, kk, ty * 4)]);
                float av[4] = {a.x, a.y, a.z, a.w};
#pragma unroll
                for (int g = 0; g < 5; g++) {
                    float2 w = *reinterpret_cast<const float2*>(&sm[BSB(ks, g, kk, tx * 2)]);
#pragma unroll
                    for (int i = 0; i < 4; i++) {
                        acc[i][g * 2 + 0] = fmaf(av[i], w.x, acc[i][g * 2 + 0]);
                        acc[i][g * 2 + 1] = fmaf(av[i], w.y, acc[i][g * 2 + 1]);
                    }
                }
            }
            __syncthreads();
        }
        // partials -> smem
#pragma unroll
        for (int i = 0; i < 4; i++)
#pragma unroll
            for (int cc = 0; cc < 10; cc++)
                sm[PART(i * 10 + cc, ks, wt)] = acc[i][cc];
        __syncthreads();
        // reduce + gates epilogue (each thread owns 2 (b,h) cells)
#pragma unroll
        for (int q = 0; q < 2; q++) {
            int c = tid + q * 256;          // 0..511
            int bl = c >> 5, hl = c & 31;
            int wti = (bl >> 2) * 16 + (hl >> 1);
            int i = bl & 3, j = hl & 1;
            int h = bn0 + hl;
            int b = bm0 + bl;
            float net[5];
#pragma unroll
            for (int g = 0; g < 5; g++) {
                int s = i * 10 + g * 2 + j;
                float v = b1[(g << 9) + h];
                v += sm[PART(s, 0, wti)] + sm[PART(s, 1, wti)]
                   + sm[PART(s, 2, wti)] + sm[PART(s, 3, wti)];
                net[g] = v;
            }
            float hx = fmaxf(net[2], 0.0f);
            float fg = 1.0f / (1.0f + expf(-net[3]));
            float ig = 1.0f / (1.0f + expf(-net[4]));
            float cn = ig * (fmaxf(net[0], 0.0f) - fmaxf(net[1], 0.0f))
                     + fg * cprev[b * H_DIM + h];
            g_c[b * H_DIM + h] = cn;
            out[((size_t)t * B_DIM + b) * H_DIM + h] = hx;
            if (t == T_DIM - 1)
                out[(size_t)TBH + (size_t)b * H_DIM + h] = cn;
        }
        grid_barrier(sense);
    }
}

// ---------------------------------------------------------------------------
// Launch: 2 kernel nodes.
// ---------------------------------------------------------------------------
extern "C" void kernel_launch(void* const* d_in, const int* in_sizes, int n_in,
                              void* d_out, int out_size)
{
    const float* x    = (const float*)d_in[0];  // [T, B, I]
    const float* cell = (const float*)d_in[1];  // [1, B, H]
    const float* W0   = (const float*)d_in[2];  // [H, H+I]
    const float* b0   = (const float*)d_in[3];  // [H]
    const float* W1   = (const float*)d_in[4];  // [5H, H]
    const float* b1   = (const float*)d_in[5];  // [5H]
    float* out = (float*)d_out;

    {
        dim3 grid(H_DIM / 64, (T_DIM * B_DIM) / 128);
        precompute_kernel<<<grid, 256>>>(x, W0, b0);
    }
    dlstm_persistent<<<NB, NT>>>(cell, W0, W1, b1, out);
}

// round 4
// speedup vs baseline: 1.4168x; 1.3592x over previous
#include <cuda_runtime.h>
#include <math.h>

#define T_DIM 512
#define B_DIM 128
#define I_DIM 512
#define H_DIM 512

#define BH (B_DIM * H_DIM)           // 65536
#define TBH (T_DIM * B_DIM * H_DIM)  // 33554432

#define NB 128   // persistent blocks (all co-resident)
#define NT 512   // 16 warps

// Dynamic smem layout (floats):
//   ws0 [512 k][8 n]        @ 0      (16 KB)  W0c slice, resident
//   ws1 [512 k][40 n]       @ 4096   (80 KB)  W1 slice, resident
//   As  [2 buf][4 ks][32 u][64 b] @ 24576 (64 KB) activation staging
//   part (aliases As)       @ 24576  phase A: [4][8][64]; phase B: [4][40][64]
#define SMEM_FLOATS 40960
#define OFF_WS1 4096
#define OFF_AS  24576

__device__ float g_A[TBH];    // precomputed x_t @ W0x^T + b0, [T*B, H]
__device__ float g_h1[BH];    // h1 for current step
__device__ float g_c[BH];     // cell state
__device__ int           g_count = 0;
__device__ volatile int  g_sense = 0;

// ---------------------------------------------------------------------------
// Grid barrier (sense reversal). 2*T_DIM = 1024 barriers/launch (even), so
// g_sense returns to 0 for the next graph replay.
// ---------------------------------------------------------------------------
__device__ __forceinline__ void grid_barrier(int& sense)
{
    __syncthreads();
    if (threadIdx.x == 0) {
        int s = sense ^ 1;
        __threadfence();
        int arrived = atomicAdd(&g_count, 1);
        if (arrived == NB - 1) {
            g_count = 0;
            __threadfence();
            g_sense = s;
        } else {
            while (g_sense != s) { }
        }
        __threadfence();
    }
    __syncthreads();
    sense ^= 1;
}

// ---------------------------------------------------------------------------
// Precompute: g_A[row, n] = x[row, :] . W0[n, 0:512] + b0[n]
// 128x64 tiles, 8x4 per thread, BK=16, 256 threads.
// ---------------------------------------------------------------------------
__global__ void __launch_bounds__(256) precompute_kernel(
    const float* __restrict__ x,
    const float* __restrict__ W0,
    const float* __restrict__ b0)
{
    __shared__ __align__(16) float Xs[16][128];
    __shared__ __align__(16) float Ws[16][64];

    const int tid = threadIdx.x;
    const int bm0 = blockIdx.y * 128;
    const int bn0 = blockIdx.x * 64;
    const int tx = tid & 15;
    const int ty = tid >> 4;

    float4 b4 = *reinterpret_cast<const float4*>(&b0[bn0 + tx * 4]);

    float acc[8][4];
#pragma unroll
    for (int i = 0; i < 8; i++)
#pragma unroll
        for (int j = 0; j < 4; j++) acc[i][j] = 0.0f;

    for (int k0 = 0; k0 < I_DIM; k0 += 16) {
#pragma unroll
        for (int i = 0; i < 2; i++) {
            int fid = tid + i * 256;
            int r = fid >> 2;
            int k4 = (fid & 3) * 4;
            float4 v = *reinterpret_cast<const float4*>(&x[(size_t)(bm0 + r) * I_DIM + k0 + k4]);
            Xs[k4 + 0][r] = v.x; Xs[k4 + 1][r] = v.y;
            Xs[k4 + 2][r] = v.z; Xs[k4 + 3][r] = v.w;
        }
        {
            int n = tid >> 2;
            int k4 = (tid & 3) * 4;
            float4 v = *reinterpret_cast<const float4*>(&W0[(size_t)(bn0 + n) * (H_DIM + I_DIM) + k0 + k4]);
            Ws[k4 + 0][n] = v.x; Ws[k4 + 1][n] = v.y;
            Ws[k4 + 2][n] = v.z; Ws[k4 + 3][n] = v.w;
        }
        __syncthreads();
#pragma unroll
        for (int k = 0; k < 16; k++) {
            float4 a0 = *reinterpret_cast<const float4*>(&Xs[k][ty * 8]);
            float4 a1 = *reinterpret_cast<const float4*>(&Xs[k][ty * 8 + 4]);
            float4 w = *reinterpret_cast<const float4*>(&Ws[k][tx * 4]);
            float av[8] = {a0.x, a0.y, a0.z, a0.w, a1.x, a1.y, a1.z, a1.w};
            float wv[4] = {w.x, w.y, w.z, w.w};
#pragma unroll
            for (int i = 0; i < 8; i++)
#pragma unroll
                for (int j = 0; j < 4; j++) acc[i][j] = fmaf(av[i], wv[j], acc[i][j]);
        }
        __syncthreads();
    }

#pragma unroll
    for (int i = 0; i < 8; i++) {
        size_t row = (size_t)(bm0 + ty * 8 + i);
        float4 v = make_float4(acc[i][0] + b4.x, acc[i][1] + b4.y,
                               acc[i][2] + b4.z, acc[i][3] + b4.w);
        *reinterpret_cast<float4*>(&g_A[row * H_DIM + bn0 + tx * 4]) = v;
    }
}

// ---------------------------------------------------------------------------
// Activation staging helpers. Chunk j of src rows [bm0, bm0+64), where the
// chunk holds, for each k-slice ks, k = ks*128 + j*32 + u (u in [0,32)).
// Thread t: b = t&63, seg = t>>6 -> (ks = seg>>1, u0 = (seg&1)*16).
// ---------------------------------------------------------------------------
__device__ __forceinline__ void stage_ldg(const float* __restrict__ src,
                                          int bm0, int j, float4 r[4])
{
    const int t = threadIdx.x;
    const int b = t & 63;
    const int seg = t >> 6;
    const int ks_s = seg >> 1;
    const int u0 = (seg & 1) * 16;
    const float* p = src + (size_t)(bm0 + b) * H_DIM + ks_s * 128 + j * 32 + u0;
    r[0] = *reinterpret_cast<const float4*>(p);
    r[1] = *reinterpret_cast<const float4*>(p + 4);
    r[2] = *reinterpret_cast<const float4*>(p + 8);
    r[3] = *reinterpret_cast<const float4*>(p + 12);
}

__device__ __forceinline__ void stage_sts(float* __restrict__ As,
                                          int buf, const float4 r[4])
{
    const int t = threadIdx.x;
    const int b = t & 63;
    const int seg = t >> 6;
    const int ks_s = seg >> 1;
    const int u0 = (seg & 1) * 16;
    float* dst = As + buf * 8192 + ks_s * 2048 + u0 * 64 + b;
#pragma unroll
    for (int i = 0; i < 4; i++) {
        dst[(i * 4 + 0) * 64] = (&r[i].x)[0];
        dst[(i * 4 + 1) * 64] = (&r[i].x)[1];
        dst[(i * 4 + 2) * 64] = (&r[i].x)[2];
        dst[(i * 4 + 3) * 64] = (&r[i].x)[3];
    }
}

// ---------------------------------------------------------------------------
// Persistent recurrence. 128 blocks x 512 threads.
// Block: bt = bid>>6 (b-rows bt*64..+64), nt = bid&63 (h-cols nt*8..+8).
// Weights resident in smem: ws0 = W0c[8 h1-cols][512 k] (as [k][8]),
// ws1 = W1 rows {g*512 + bn0h + hl : g<5, hl<8} (as [k][40], n = g*8+hl).
// Warp (16) = (ks = w>>2, bh = (w>>1)&1, ng = w&1):
//   phase A: tile 32b x 4n,  k-slice 128; phase B: tile 32b x 20n, k-slice 128.
// ---------------------------------------------------------------------------
__global__ void __launch_bounds__(NT, 1) dlstm_persistent(
    const float* __restrict__ cell,
    const float* __restrict__ W0,   // [512][1024]
    const float* __restrict__ W1,   // [2560][512]
    const float* __restrict__ b1,   // [2560]
    float* __restrict__ out)        // [T][B][H] then [B][H] final cell
{
    extern __shared__ __align__(16) float sm[];
    float* ws0 = sm;
    float* ws1 = sm + OFF_WS1;
    float* As  = sm + OFF_AS;
    float* part = sm + OFF_AS;

    const int tid = threadIdx.x;
    const int lane = tid & 31;
    const int warp = tid >> 5;
    const int ks = warp >> 2;          // 0..3  k-slice
    const int bh = (warp >> 1) & 1;    // 0..1  b-half
    const int ng = warp & 1;           // 0..1  n-group

    const int bid = blockIdx.x;
    const int bm0 = (bid >> 6) * 64;   // b-rows
    const int bn0h = (bid & 63) * 8;   // h-cols

    // ---- Preload resident weights (once) ----
    {
        int k = tid;  // 512 threads = 512 k values
#pragma unroll
        for (int n = 0; n < 8; n++)
            ws0[k * 8 + n] = W0[(size_t)(bn0h + n) * (H_DIM + I_DIM) + I_DIM + k];
#pragma unroll
        for (int n = 0; n < 40; n++) {
            int g = n >> 3, hl = n & 7;
            ws1[k * 40 + n] = W1[(size_t)(g * H_DIM + bn0h + hl) * H_DIM + k];
        }
    }
    __syncthreads();

    int sense = 0;

    for (int t = 0; t < T_DIM; t++) {
        const float* cprev = (t == 0) ? cell : (const float*)g_c;

        // ================= Phase A: h1 = relu(g_A[t] + c @ W0c^T) ==========
        {
            float acca[4] = {0.f, 0.f, 0.f, 0.f};
            float4 r[4];
            stage_ldg(cprev, bm0, 0, r);
            stage_sts(As, 0, r);
            for (int j = 0; j < 4; j++) {
                if (j < 3) stage_ldg(cprev, bm0, j + 1, r);
                __syncthreads();
                const float* a_base = As + (j & 1) * 8192 + ks * 2048 + bh * 32 + lane;
                const float* w_base = ws0 + (ks * 128 + j * 32) * 8 + ng * 4;
#pragma unroll
                for (int u = 0; u < 32; u++) {
                    float a = a_base[u * 64];
                    float4 w = *reinterpret_cast<const float4*>(w_base + u * 8);
                    acca[0] = fmaf(a, w.x, acca[0]);
                    acca[1] = fmaf(a, w.y, acca[1]);
                    acca[2] = fmaf(a, w.z, acca[2]);
                    acca[3] = fmaf(a, w.w, acca[3]);
                }
                __syncthreads();
                if (j < 3) stage_sts(As, (j + 1) & 1, r);
            }
            // partials (alias As; safe after the final post-compute sync)
#pragma unroll
            for (int jj = 0; jj < 4; jj++)
                part[ks * 512 + (ng * 4 + jj) * 64 + bh * 32 + lane] = acca[jj];
            __syncthreads();
            // reduce + add precomputed + relu -> g_h1
            {
                int b = tid & 63;
                int n = tid >> 6;  // 0..7
                float v = part[n * 64 + b] + part[512 + n * 64 + b]
                        + part[1024 + n * 64 + b] + part[1536 + n * 64 + b];
                v += g_A[((size_t)t * B_DIM + bm0 + b) * H_DIM + bn0h + n];
                g_h1[(bm0 + b) * H_DIM + bn0h + n] = fmaxf(v, 0.0f);
            }
        }
        grid_barrier(sense);

        // ================= Phase B: 5-gate GEMM + fused epilogue ===========
        {
            float acc[20];
#pragma unroll
            for (int i = 0; i < 20; i++) acc[i] = 0.0f;
            float4 r[4];
            stage_ldg((const float*)g_h1, bm0, 0, r);
            stage_sts(As, 0, r);
            for (int j = 0; j < 4; j++) {
                if (j < 3) stage_ldg((const float*)g_h1, bm0, j + 1, r);
                __syncthreads();
                const float* a_base = As + (j & 1) * 8192 + ks * 2048 + bh * 32 + lane;
                const float* w_base = ws1 + (ks * 128 + j * 32) * 40 + ng * 20;
#pragma unroll
                for (int u = 0; u < 32; u++) {
                    float a = a_base[u * 64];
                    const float* wp = w_base + u * 40;
                    float4 w0 = *reinterpret_cast<const float4*>(wp);
                    float4 w1v = *reinterpret_cast<const float4*>(wp + 4);
                    float4 w2 = *reinterpret_cast<const float4*>(wp + 8);
                    float4 w3 = *reinterpret_cast<const float4*>(wp + 12);
                    float4 w4 = *reinterpret_cast<const float4*>(wp + 16);
                    acc[0]  = fmaf(a, w0.x,  acc[0]);  acc[1]  = fmaf(a, w0.y,  acc[1]);
                    acc[2]  = fmaf(a, w0.z,  acc[2]);  acc[3]  = fmaf(a, w0.w,  acc[3]);
                    acc[4]  = fmaf(a, w1v.x, acc[4]);  acc[5]  = fmaf(a, w1v.y, acc[5]);
                    acc[6]  = fmaf(a, w1v.z, acc[6]);  acc[7]  = fmaf(a, w1v.w, acc[7]);
                    acc[8]  = fmaf(a, w2.x,  acc[8]);  acc[9]  = fmaf(a, w2.y,  acc[9]);
                    acc[10] = fmaf(a, w2.z,  acc[10]); acc[11] = fmaf(a, w2.w,  acc[11]);
                    acc[12] = fmaf(a, w3.x,  acc[12]); acc[13] = fmaf(a, w3.y,  acc[13]);
                    acc[14] = fmaf(a, w3.z,  acc[14]); acc[15] = fmaf(a, w3.w,  acc[15]);
                    acc[16] = fmaf(a, w4.x,  acc[16]); acc[17] = fmaf(a, w4.y,  acc[17]);
                    acc[18] = fmaf(a, w4.z,  acc[18]); acc[19] = fmaf(a, w4.w,  acc[19]);
                }
                __syncthreads();
                if (j < 3) stage_sts(As, (j + 1) & 1, r);
            }
            // partials
#pragma unroll
            for (int jj = 0; jj < 20; jj++)
                part[ks * 2560 + (ng * 20 + jj) * 64 + bh * 32 + lane] = acc[jj];
            __syncthreads();
            // reduce + gates epilogue: thread owns cell (b, hl)
            {
                int b = tid & 63;
                int hl = tid >> 6;  // 0..7
                int hg = bn0h + hl;
                int bg = bm0 + b;
                float net[5];
#pragma unroll
                for (int g = 0; g < 5; g++) {
                    int n = g * 8 + hl;
                    float v = b1[g * H_DIM + hg];
                    v += part[n * 64 + b] + part[2560 + n * 64 + b]
                       + part[5120 + n * 64 + b] + part[7680 + n * 64 + b];
                    net[g] = v;
                }
                float hx = fmaxf(net[2], 0.0f);
                float fg = 1.0f / (1.0f + expf(-net[3]));
                float ig = 1.0f / (1.0f + expf(-net[4]));
                float cn = ig * (fmaxf(net[0], 0.0f) - fmaxf(net[1], 0.0f))
                         + fg * cprev[bg * H_DIM + hg];
                g_c[bg * H_DIM + hg] = cn;
                out[((size_t)t * B_DIM + bg) * H_DIM + hg] = hx;
                if (t == T_DIM - 1)
                    out[(size_t)TBH + (size_t)bg * H_DIM + hg] = cn;
            }
        }
        grid_barrier(sense);
    }
}

// ---------------------------------------------------------------------------
// Launch: 2 kernel nodes.
// ---------------------------------------------------------------------------
extern "C" void kernel_launch(void* const* d_in, const int* in_sizes, int n_in,
                              void* d_out, int out_size)
{
    const float* x    = (const float*)d_in[0];  // [T, B, I]
    const float* cell = (const float*)d_in[1];  // [1, B, H]
    const float* W0   = (const float*)d_in[2];  // [H, H+I]
    const float* b0   = (const float*)d_in[3];  // [H]
    const float* W1   = (const float*)d_in[4];  // [5H, H]
    const float* b1   = (const float*)d_in[5];  // [5H]
    float* out = (float*)d_out;

    static int configured = 0;
    if (!configured) {
        cudaFuncSetAttribute(dlstm_persistent,
                             cudaFuncAttributeMaxDynamicSharedMemorySize,
                             SMEM_FLOATS * (int)sizeof(float));
        configured = 1;
    }

    {
        dim3 grid(H_DIM / 64, (T_DIM * B_DIM) / 128);
        precompute_kernel<<<grid, 256>>>(x, W0, b0);
    }
    dlstm_persistent<<<NB, NT, SMEM_FLOATS * sizeof(float)>>>(cell, W0, W1, b1, out);
}